// round 9
// baseline (speedup 1.0000x reference)
#include <cuda_runtime.h>
#include <cstdint>

#define Tq   1024
#define F_IN 64
#define HDIM 40
#define G4   160

typedef unsigned long long ull;

// ---- global scratch (no allocation allowed; __device__ arrays) ----
__device__ float g_xa[(size_t)512 * Tq * G4];     // seq @ WaK + ba
__device__ float g_xb[(size_t)512 * Tq * G4];     // hs  @ WbK + bb
__device__ float g_hs[(size_t)512 * Tq * HDIM];   // LSTM A outputs
__device__ float g_hlast[512 * HDIM];             // LSTM B final h

// ---------------------------------------------------------------------------
// Packed f32x2 helpers
// ---------------------------------------------------------------------------
__device__ __forceinline__ ull pack2(float a, float b) {
    ull r; asm("mov.b64 %0, {%1,%2};" : "=l"(r) : "f"(a), "f"(b)); return r;
}
__device__ __forceinline__ void unpack2(ull v, float& a, float& b) {
    asm("mov.b64 {%0,%1}, %2;" : "=f"(a), "=f"(b) : "l"(v));
}
__device__ __forceinline__ void ffma2(ull& d, ull a, ull b) {
    asm("fma.rn.f32x2 %0, %1, %2, %0;" : "+l"(d) : "l"(a), "l"(b));
}

// ---------------------------------------------------------------------------
// MUFU activations
// ---------------------------------------------------------------------------
__device__ __forceinline__ float sigmoid_f(float x) {
    float e, r;
    asm("ex2.approx.f32 %0, %1;" : "=f"(e) : "f"(-1.4426950408889634f * x));
    asm("rcp.approx.f32 %0, %1;" : "=f"(r) : "f"(1.0f + e));
    return r;
}
__device__ __forceinline__ float tanh_f(float x) {
    float e, r;
    asm("ex2.approx.f32 %0, %1;" : "=f"(e) : "f"(2.8853900817779268f * x));
    asm("rcp.approx.f32 %0, %1;" : "=f"(r) : "f"(1.0f + e));
    return 1.0f - 2.0f * r;
}
__device__ __forceinline__ float gate_act(float z, float mm, float aa, float bb) {
    float e, r;
    asm("ex2.approx.f32 %0, %1;" : "=f"(e) : "f"(mm * z));
    asm("rcp.approx.f32 %0, %1;" : "=f"(r) : "f"(1.0f + e));
    return fmaf(aa, r, bb);
}

__device__ __forceinline__ unsigned smem_u32(const void* p) {
    return (unsigned)__cvta_generic_to_shared(p);
}

// ===========================================================================
// K1: xa[b,t,g] = seq[b,t,:]·WaK[:,g] + ba[g].  Barrier-free GEMM.
// grid (512, 4): block = (row b, 256-step chunk). 160 threads = columns.
// x rows loaded by broadcast LDG.128 (all lanes same address); weights in
// registers as f32x2 pairs; 2 rows in flight for MLP.
// ===========================================================================
__global__ void __launch_bounds__(160)
xa_gemm(const float* __restrict__ seq, const float* __restrict__ WaK,
        const float* __restrict__ ba)
{
    const int b = blockIdx.x, ch = blockIdx.y, g = threadIdx.x;
    ull wk2[32];
    #pragma unroll
    for (int p = 0; p < 32; p++)
        wk2[p] = pack2(WaK[(2 * p) * G4 + g], WaK[(2 * p + 1) * G4 + g]);
    const float bias = ba[g];

    const size_t base = (size_t)b * Tq + (size_t)ch * 256;
    const ulonglong2* rp = (const ulonglong2*)(seq + base * F_IN);
    float* op = g_xa + base * G4 + g;

    for (int t = 0; t < 256; t += 2) {
        const ulonglong2* r0 = rp + (size_t)t * 16;   // 64 floats = 16x16B
        const ulonglong2* r1 = r0 + 16;
        ull a0 = 0, a1 = 0, c0 = 0, c1 = 0;
        #pragma unroll
        for (int p = 0; p < 16; p++) {
            ulonglong2 v0 = r0[p], v1 = r1[p];
            ffma2(a0, wk2[2 * p],     v0.x);
            ffma2(a1, wk2[2 * p + 1], v0.y);
            ffma2(c0, wk2[2 * p],     v1.x);
            ffma2(c1, wk2[2 * p + 1], v1.y);
        }
        float x0, x1, x2, x3;
        unpack2(a0, x0, x1); unpack2(a1, x2, x3);
        op[(size_t)t * G4] = bias + ((x0 + x2) + (x1 + x3));
        unpack2(c0, x0, x1); unpack2(c1, x2, x3);
        op[(size_t)(t + 1) * G4] = bias + ((x0 + x2) + (x1 + x3));
    }
}

// ===========================================================================
// K3: xb[b,t,g] = hs[b,t,:]·WbK[:,g] + bb[g].  Same design, 40-long dot.
// ===========================================================================
__global__ void __launch_bounds__(160)
xb_gemm(const float* __restrict__ WbK, const float* __restrict__ bb)
{
    const int b = blockIdx.x, ch = blockIdx.y, g = threadIdx.x;
    ull wk2[20];
    #pragma unroll
    for (int p = 0; p < 20; p++)
        wk2[p] = pack2(WbK[(2 * p) * G4 + g], WbK[(2 * p + 1) * G4 + g]);
    const float bias = bb[g];

    const size_t base = (size_t)b * Tq + (size_t)ch * 256;
    const ulonglong2* rp = (const ulonglong2*)(g_hs + base * HDIM);
    float* op = g_xb + base * G4 + g;

    for (int t = 0; t < 256; t += 2) {
        const ulonglong2* r0 = rp + (size_t)t * 10;   // 40 floats = 10x16B
        const ulonglong2* r1 = r0 + 10;
        ull a0 = 0, a1 = 0, c0 = 0, c1 = 0;
        #pragma unroll
        for (int p = 0; p < 10; p++) {
            ulonglong2 v0 = r0[p], v1 = r1[p];
            ffma2(a0, wk2[2 * p],     v0.x);
            ffma2(a1, wk2[2 * p + 1], v0.y);
            ffma2(c0, wk2[2 * p],     v1.x);
            ffma2(c1, wk2[2 * p + 1], v1.y);
        }
        float x0, x1, x2, x3;
        unpack2(a0, x0, x1); unpack2(a1, x2, x3);
        op[(size_t)t * G4] = bias + ((x0 + x2) + (x1 + x3));
        unpack2(c0, x0, x1); unpack2(c1, x2, x3);
        op[(size_t)(t + 1) * G4] = bias + ((x0 + x2) + (x1 + x3));
    }
}

// ===========================================================================
// K2/K4: minimal LSTM recurrence. grid 512 (one batch row per block),
// 160 threads: warp w owns hidden units [8w,8w+8); lane = q*8+u computes the
// q-th gate of unit j=8w+u (weight column col=q*40+j in registers).
// Per step: xz from cp.async ring + 40-long h-dot (double-buffered smem h),
// gate exchange via shfl_xor, q==0 lane updates c and writes h. One 5-warp
// barrier per step; 3-4 independent blocks/SM hide each other's stalls.
// MODE 0: source g_xa, write every h to g_hs.  MODE 1: source g_xb, write
// only the final h to g_hlast.
// ===========================================================================
template<int MODE>
__global__ void __launch_bounds__(160)
recur_k(const float* __restrict__ Wr)
{
    __shared__ __align__(16) float sxa[8][G4];    // ring: 8 x 640 B
    __shared__ __align__(16) float sh[2][HDIM];   // double-buffered h

    const int b = blockIdx.x, tid = threadIdx.x;
    const int lane = tid & 31, q = lane >> 3, u = lane & 7, w = tid >> 5;
    const int j = w * 8 + u;
    const int col = q * HDIM + j;

    const bool isG = (q == 2);
    const float mm  = isG ? -2.8853900817779268f : -1.4426950408889634f;
    const float aa  = isG ? 2.0f : 1.0f;
    const float bbv = isG ? -1.0f : 0.0f;

    ull wr2[20];
    #pragma unroll
    for (int p = 0; p < 20; p++)
        wr2[p] = pack2(Wr[(2 * p) * G4 + col], Wr[(2 * p + 1) * G4 + col]);

    float c = 0.0f;
    if (tid < HDIM) sh[0][tid] = 0.0f;

    const float* srcb = (MODE == 0 ? g_xa : g_xb) + (size_t)b * Tq * G4;

    // ring prologue: threads 0..39 each own one 16B chunk of the 640B row
    if (tid < 40) {
        #pragma unroll
        for (int p = 0; p < 4; p++) {
            unsigned dst = smem_u32(&sxa[p][tid * 4]);
            asm volatile("cp.async.ca.shared.global [%0], [%1], 16;\n\t"
                         "cp.async.commit_group;\n"
                         :: "r"(dst), "l"(srcb + (size_t)p * G4 + tid * 4));
        }
        asm volatile("cp.async.wait_group 3;");   // slot 0 ready
    }
    __syncthreads();

    for (int t = 0; t < Tq; t++) {
        if (tid < 40) {
            const int tf = t + 4;
            if (tf < Tq) {
                unsigned dst = smem_u32(&sxa[tf & 7][tid * 4]);
                asm volatile("cp.async.ca.shared.global [%0], [%1], 16;"
                             :: "r"(dst), "l"(srcb + (size_t)tf * G4 + tid * 4));
            }
            asm volatile("cp.async.commit_group;\n\t"
                         "cp.async.wait_group 3;\n");   // slots <= t+1 done
        }

        const float xz = sxa[t & 7][col];
        const ulonglong2* h2 = (const ulonglong2*)sh[t & 1];
        ull a0 = 0ull, a1 = 0ull;
        #pragma unroll
        for (int p = 0; p < 10; p++) {
            ulonglong2 hv = h2[p];
            ffma2(a0, wr2[2 * p],     hv.x);
            ffma2(a1, wr2[2 * p + 1], hv.y);
        }
        float x0, x1, x2, x3;
        unpack2(a0, x0, x1); unpack2(a1, x2, x3);
        const float z = xz + ((x0 + x2) + (x1 + x3));
        const float v = gate_act(z, mm, aa, bbv);

        const float fv = __shfl_xor_sync(0xffffffffu, v, 8);
        const float gv = __shfl_xor_sync(0xffffffffu, v, 16);
        const float ov = __shfl_xor_sync(0xffffffffu, v, 24);
        if (q == 0) {
            c = fmaf(fv, c, v * gv);
            const float h = ov * tanh_f(c);
            sh[(t + 1) & 1][j] = h;
            if (MODE == 0)
                g_hs[((size_t)b * Tq + t) * HDIM + j] = h;
            else if (t == Tq - 1)
                g_hlast[b * HDIM + j] = h;
        }
        __syncthreads();
    }
}

// ===========================================================================
// K5: dense tail. grid 128 x 160 threads, 4 rows/block.
// ===========================================================================
__global__ void __launch_bounds__(160)
tail_k(const float* __restrict__ feat,
       const float* __restrict__ Wg, const float* __restrict__ bg,
       const float* __restrict__ Wh, const float* __restrict__ bh,
       const float* __restrict__ Wc, const float* __restrict__ bc,
       const float* __restrict__ Wd, const float* __restrict__ bd,
       const float* __restrict__ Wo, const float* __restrict__ bo,
       float* __restrict__ out)
{
    __shared__ float hB[4][HDIM];
    __shared__ float t1[4][10], yy[4][10], cc[4][20], dd[4][10];
    const int tid = threadIdx.x, b4 = blockIdx.x * 4;
    const int r = tid / HDIM, uu = tid % HDIM;

    hB[r][uu] = g_hlast[(b4 + r) * HDIM + uu];
    __syncthreads();

    const float* fb = feat + (size_t)(b4 + r) * F_IN;
    if (uu < 10) {
        float a = bg[uu];
        #pragma unroll 8
        for (int k = 0; k < F_IN; k++) a = fmaf(fb[k], Wg[k * 10 + uu], a);
        t1[r][uu] = tanh_f(a);
    }
    __syncthreads();
    if (uu < 10) {
        float a = bh[uu];
        #pragma unroll
        for (int k = 0; k < 10; k++) a = fmaf(t1[r][k], Wh[k * 10 + uu], a);
        yy[r][uu] = tanh_f(a);
    }
    __syncthreads();
    if (uu < 20) {
        float a = bc[uu];
        #pragma unroll
        for (int k = 0; k < HDIM; k++) a = fmaf(hB[r][k], Wc[k * 20 + uu], a);
        #pragma unroll
        for (int k = 0; k < 10; k++)   a = fmaf(yy[r][k], Wc[(HDIM + k) * 20 + uu], a);
        cc[r][uu] = fmaxf(a, 0.0f);
    }
    __syncthreads();
    if (uu < 10) {
        float a = bd[uu];
        #pragma unroll
        for (int k = 0; k < 20; k++) a = fmaf(cc[r][k], Wd[k * 10 + uu], a);
        dd[r][uu] = fmaxf(a, 0.0f);
    }
    __syncthreads();
    if (uu == 0) {
        float a = bo[0];
        #pragma unroll
        for (int k = 0; k < 10; k++) a = fmaf(dd[r][k], Wo[k], a);
        out[b4 + r] = sigmoid_f(a);
    }
}

// ---------------------------------------------------------------------------
extern "C" void kernel_launch(void* const* d_in, const int* in_sizes, int n_in,
                              void* d_out, int out_size)
{
    (void)in_sizes; (void)n_in; (void)out_size;
    const float* seq  = (const float*)d_in[0];
    const float* feat = (const float*)d_in[1];
    const float* WaK  = (const float*)d_in[2];
    const float* WaR  = (const float*)d_in[3];
    const float* ba   = (const float*)d_in[4];
    const float* WbK  = (const float*)d_in[5];
    const float* WbR  = (const float*)d_in[6];
    const float* bb   = (const float*)d_in[7];
    const float* Wg   = (const float*)d_in[8];
    const float* bg   = (const float*)d_in[9];
    const float* Wh   = (const float*)d_in[10];
    const float* bh   = (const float*)d_in[11];
    const float* Wc   = (const float*)d_in[12];
    const float* bc   = (const float*)d_in[13];
    const float* Wd   = (const float*)d_in[14];
    const float* bd   = (const float*)d_in[15];
    const float* Wo   = (const float*)d_in[16];
    const float* bo   = (const float*)d_in[17];
    float* out = (float*)d_out;

    xa_gemm<<<dim3(512, 4), 160>>>(seq, WaK, ba);
    recur_k<0><<<512, 160>>>(WaR);
    xb_gemm<<<dim3(512, 4), 160>>>(WbK, bb);
    recur_k<1><<<512, 160>>>(WbR);
    tail_k<<<128, 160>>>(feat, Wg, bg, Wh, bh, Wc, bc, Wd, bd, Wo, bo, out);
}

// round 10
// speedup vs baseline: 1.9518x; 1.9518x over previous
#include <cuda_runtime.h>
#include <cstdint>

#define Tq   1024
#define F_IN 64
#define HDIM 40
#define G4   160

typedef unsigned long long ull;

// ---- global scratch (no allocation allowed; __device__ arrays) ----
__device__ float g_xa[(size_t)512 * Tq * G4];     // seq @ WaK + ba
__device__ float g_xb[(size_t)512 * Tq * G4];     // hs  @ WbK + bb
__device__ float g_hs[(size_t)512 * Tq * HDIM];   // LSTM A outputs
__device__ float g_hlast[512 * HDIM];             // LSTM B final h

// ---------------------------------------------------------------------------
// Packed f32x2 helpers
// ---------------------------------------------------------------------------
__device__ __forceinline__ ull pack2(float a, float b) {
    ull r; asm("mov.b64 %0, {%1,%2};" : "=l"(r) : "f"(a), "f"(b)); return r;
}
__device__ __forceinline__ void unpack2(ull v, float& a, float& b) {
    asm("mov.b64 {%0,%1}, %2;" : "=f"(a), "=f"(b) : "l"(v));
}
__device__ __forceinline__ void ffma2(ull& d, ull a, ull b) {
    asm("fma.rn.f32x2 %0, %1, %2, %0;" : "+l"(d) : "l"(a), "l"(b));
}

// ---------------------------------------------------------------------------
// MUFU activations
// ---------------------------------------------------------------------------
__device__ __forceinline__ float sigmoid_f(float x) {
    float e, r;
    asm("ex2.approx.f32 %0, %1;" : "=f"(e) : "f"(-1.4426950408889634f * x));
    asm("rcp.approx.f32 %0, %1;" : "=f"(r) : "f"(1.0f + e));
    return r;
}
__device__ __forceinline__ float tanh_f(float x) {
    float e, r;
    asm("ex2.approx.f32 %0, %1;" : "=f"(e) : "f"(2.8853900817779268f * x));
    asm("rcp.approx.f32 %0, %1;" : "=f"(r) : "f"(1.0f + e));
    return 1.0f - 2.0f * r;
}
__device__ __forceinline__ float gate_act(float z, float mm, float aa, float bb) {
    float e, r;
    asm("ex2.approx.f32 %0, %1;" : "=f"(e) : "f"(mm * z));
    asm("rcp.approx.f32 %0, %1;" : "=f"(r) : "f"(1.0f + e));
    return fmaf(aa, r, bb);
}

__device__ __forceinline__ unsigned smem_u32(const void* p) {
    return (unsigned)__cvta_generic_to_shared(p);
}

// ===========================================================================
// K1: xa[b,t,g] = seq[b,t,:]·WaK[:,g] + ba[g].
// grid (512, 4): block = (row b, 256-step chunk), 160 threads = columns.
// 32-row x tiles staged in smem via coalesced LDG.128 (once), consumed via
// broadcast LDS.128 — removes the per-warp redundant-LDG LSU bottleneck that
// killed R9. Weights in registers; 2 output rows in flight for ILP.
// ===========================================================================
__global__ void __launch_bounds__(160)
xa_gemm(const float* __restrict__ seq, const float* __restrict__ WaK,
        const float* __restrict__ ba)
{
    __shared__ __align__(16) float4 sx[32 * 16];   // 32 rows x 64 floats = 8KB
    const int b = blockIdx.x, ch = blockIdx.y, g = threadIdx.x;

    ull wk2[32];
    #pragma unroll
    for (int p = 0; p < 32; p++)
        wk2[p] = pack2(WaK[(2 * p) * G4 + g], WaK[(2 * p + 1) * G4 + g]);
    const float bias = ba[g];

    const size_t base = (size_t)b * Tq + (size_t)ch * 256;
    const float4* src = (const float4*)(seq + base * F_IN);
    float* op = g_xa + base * G4 + g;

    for (int tile = 0; tile < 8; tile++) {
        // stage 32 rows (512 float4) cooperatively, coalesced
        const float4* s4 = src + (size_t)tile * 512;
        #pragma unroll
        for (int i = 0; i < 4; i++) {
            const int idx = g + i * 160;
            if (idx < 512) sx[idx] = s4[idx];
        }
        __syncthreads();

        #pragma unroll 2
        for (int r = 0; r < 32; r += 2) {
            const ulonglong2* r0 = (const ulonglong2*)&sx[r * 16];
            const ulonglong2* r1 = (const ulonglong2*)&sx[(r + 1) * 16];
            ull a0 = 0, a1 = 0, c0 = 0, c1 = 0;
            #pragma unroll
            for (int p = 0; p < 16; p++) {
                ulonglong2 v0 = r0[p], v1 = r1[p];
                ffma2(a0, wk2[2 * p],     v0.x);
                ffma2(a1, wk2[2 * p + 1], v0.y);
                ffma2(c0, wk2[2 * p],     v1.x);
                ffma2(c1, wk2[2 * p + 1], v1.y);
            }
            float x0, x1, x2, x3;
            unpack2(a0, x0, x1); unpack2(a1, x2, x3);
            op[(size_t)(tile * 32 + r) * G4] = bias + ((x0 + x2) + (x1 + x3));
            unpack2(c0, x0, x1); unpack2(c1, x2, x3);
            op[(size_t)(tile * 32 + r + 1) * G4] = bias + ((x0 + x2) + (x1 + x3));
        }
        __syncthreads();
    }
}

// ===========================================================================
// K3: xb[b,t,g] = hs[b,t,:]·WbK[:,g] + bb[g].  Same design; 64-row tiles of
// 40-float hs rows (10KB smem), 40-long dots.
// ===========================================================================
__global__ void __launch_bounds__(160)
xb_gemm(const float* __restrict__ WbK, const float* __restrict__ bb)
{
    __shared__ __align__(16) float4 sh4[64 * 10];  // 64 rows x 40 floats = 10KB
    const int b = blockIdx.x, ch = blockIdx.y, g = threadIdx.x;

    ull wk2[20];
    #pragma unroll
    for (int p = 0; p < 20; p++)
        wk2[p] = pack2(WbK[(2 * p) * G4 + g], WbK[(2 * p + 1) * G4 + g]);
    const float bias = bb[g];

    const size_t base = (size_t)b * Tq + (size_t)ch * 256;
    const float4* src = (const float4*)(g_hs + base * HDIM);
    float* op = g_xb + base * G4 + g;

    for (int tile = 0; tile < 4; tile++) {
        // stage 64 rows (640 float4) cooperatively
        const float4* s4 = src + (size_t)tile * 640;
        #pragma unroll
        for (int i = 0; i < 4; i++) sh4[g + i * 160] = s4[g + i * 160];
        __syncthreads();

        #pragma unroll 2
        for (int r = 0; r < 64; r += 2) {
            const ulonglong2* r0 = (const ulonglong2*)&sh4[r * 10];
            const ulonglong2* r1 = (const ulonglong2*)&sh4[(r + 1) * 10];
            ull a0 = 0, a1 = 0, c0 = 0, c1 = 0;
            #pragma unroll
            for (int p = 0; p < 10; p++) {
                ulonglong2 v0 = r0[p], v1 = r1[p];
                ffma2(a0, wk2[2 * p],     v0.x);
                ffma2(a1, wk2[2 * p + 1], v0.y);
                ffma2(c0, wk2[2 * p],     v1.x);
                ffma2(c1, wk2[2 * p + 1], v1.y);
            }
            float x0, x1, x2, x3;
            unpack2(a0, x0, x1); unpack2(a1, x2, x3);
            op[(size_t)(tile * 64 + r) * G4] = bias + ((x0 + x2) + (x1 + x3));
            unpack2(c0, x0, x1); unpack2(c1, x2, x3);
            op[(size_t)(tile * 64 + r + 1) * G4] = bias + ((x0 + x2) + (x1 + x3));
        }
        __syncthreads();
    }
}

// ===========================================================================
// K2/K4: minimal LSTM recurrence (unchanged from R9 — verified 453us each).
// grid 512 (one batch row per block), 160 threads; warp w owns units
// [8w,8w+8); lane q*8+u computes gate q of unit j=8w+u. xz from cp.async
// ring; 40-long h-dot on double-buffered smem h; shfl gate exchange; one
// barrier per step. MODE 0: g_xa -> g_hs.  MODE 1: g_xb -> g_hlast.
// ===========================================================================
template<int MODE>
__global__ void __launch_bounds__(160)
recur_k(const float* __restrict__ Wr)
{
    __shared__ __align__(16) float sxa[8][G4];    // ring: 8 x 640 B
    __shared__ __align__(16) float sh[2][HDIM];   // double-buffered h

    const int b = blockIdx.x, tid = threadIdx.x;
    const int lane = tid & 31, q = lane >> 3, u = lane & 7, w = tid >> 5;
    const int j = w * 8 + u;
    const int col = q * HDIM + j;

    const bool isG = (q == 2);
    const float mm  = isG ? -2.8853900817779268f : -1.4426950408889634f;
    const float aa  = isG ? 2.0f : 1.0f;
    const float bbv = isG ? -1.0f : 0.0f;

    ull wr2[20];
    #pragma unroll
    for (int p = 0; p < 20; p++)
        wr2[p] = pack2(Wr[(2 * p) * G4 + col], Wr[(2 * p + 1) * G4 + col]);

    float c = 0.0f;
    if (tid < HDIM) sh[0][tid] = 0.0f;

    const float* srcb = (MODE == 0 ? g_xa : g_xb) + (size_t)b * Tq * G4;

    // ring prologue: threads 0..39 each own one 16B chunk of the 640B row
    if (tid < 40) {
        #pragma unroll
        for (int p = 0; p < 4; p++) {
            unsigned dst = smem_u32(&sxa[p][tid * 4]);
            asm volatile("cp.async.ca.shared.global [%0], [%1], 16;\n\t"
                         "cp.async.commit_group;\n"
                         :: "r"(dst), "l"(srcb + (size_t)p * G4 + tid * 4));
        }
        asm volatile("cp.async.wait_group 3;");   // slot 0 ready
    }
    __syncthreads();

    for (int t = 0; t < Tq; t++) {
        if (tid < 40) {
            const int tf = t + 4;
            if (tf < Tq) {
                unsigned dst = smem_u32(&sxa[tf & 7][tid * 4]);
                asm volatile("cp.async.ca.shared.global [%0], [%1], 16;"
                             :: "r"(dst), "l"(srcb + (size_t)tf * G4 + tid * 4));
            }
            asm volatile("cp.async.commit_group;\n\t"
                         "cp.async.wait_group 3;\n");   // slots <= t+1 done
        }

        const float xz = sxa[t & 7][col];
        const ulonglong2* h2 = (const ulonglong2*)sh[t & 1];
        ull a0 = 0ull, a1 = 0ull;
        #pragma unroll
        for (int p = 0; p < 10; p++) {
            ulonglong2 hv = h2[p];
            ffma2(a0, wr2[2 * p],     hv.x);
            ffma2(a1, wr2[2 * p + 1], hv.y);
        }
        float x0, x1, x2, x3;
        unpack2(a0, x0, x1); unpack2(a1, x2, x3);
        const float z = xz + ((x0 + x2) + (x1 + x3));
        const float v = gate_act(z, mm, aa, bbv);

        const float fv = __shfl_xor_sync(0xffffffffu, v, 8);
        const float gv = __shfl_xor_sync(0xffffffffu, v, 16);
        const float ov = __shfl_xor_sync(0xffffffffu, v, 24);
        if (q == 0) {
            c = fmaf(fv, c, v * gv);
            const float h = ov * tanh_f(c);
            sh[(t + 1) & 1][j] = h;
            if (MODE == 0)
                g_hs[((size_t)b * Tq + t) * HDIM + j] = h;
            else if (t == Tq - 1)
                g_hlast[b * HDIM + j] = h;
        }
        __syncthreads();
    }
}

// ===========================================================================
// K5: dense tail. grid 128 x 160 threads, 4 rows/block.
// ===========================================================================
__global__ void __launch_bounds__(160)
tail_k(const float* __restrict__ feat,
       const float* __restrict__ Wg, const float* __restrict__ bg,
       const float* __restrict__ Wh, const float* __restrict__ bh,
       const float* __restrict__ Wc, const float* __restrict__ bc,
       const float* __restrict__ Wd, const float* __restrict__ bd,
       const float* __restrict__ Wo, const float* __restrict__ bo,
       float* __restrict__ out)
{
    __shared__ float hB[4][HDIM];
    __shared__ float t1[4][10], yy[4][10], cc[4][20], dd[4][10];
    const int tid = threadIdx.x, b4 = blockIdx.x * 4;
    const int r = tid / HDIM, uu = tid % HDIM;

    hB[r][uu] = g_hlast[(b4 + r) * HDIM + uu];
    __syncthreads();

    const float* fb = feat + (size_t)(b4 + r) * F_IN;
    if (uu < 10) {
        float a = bg[uu];
        #pragma unroll 8
        for (int k = 0; k < F_IN; k++) a = fmaf(fb[k], Wg[k * 10 + uu], a);
        t1[r][uu] = tanh_f(a);
    }
    __syncthreads();
    if (uu < 10) {
        float a = bh[uu];
        #pragma unroll
        for (int k = 0; k < 10; k++) a = fmaf(t1[r][k], Wh[k * 10 + uu], a);
        yy[r][uu] = tanh_f(a);
    }
    __syncthreads();
    if (uu < 20) {
        float a = bc[uu];
        #pragma unroll
        for (int k = 0; k < HDIM; k++) a = fmaf(hB[r][k], Wc[k * 20 + uu], a);
        #pragma unroll
        for (int k = 0; k < 10; k++)   a = fmaf(yy[r][k], Wc[(HDIM + k) * 20 + uu], a);
        cc[r][uu] = fmaxf(a, 0.0f);
    }
    __syncthreads();
    if (uu < 10) {
        float a = bd[uu];
        #pragma unroll
        for (int k = 0; k < 20; k++) a = fmaf(cc[r][k], Wd[k * 10 + uu], a);
        dd[r][uu] = fmaxf(a, 0.0f);
    }
    __syncthreads();
    if (uu == 0) {
        float a = bo[0];
        #pragma unroll
        for (int k = 0; k < 10; k++) a = fmaf(dd[r][k], Wo[k], a);
        out[b4 + r] = sigmoid_f(a);
    }
}

// ---------------------------------------------------------------------------
extern "C" void kernel_launch(void* const* d_in, const int* in_sizes, int n_in,
                              void* d_out, int out_size)
{
    (void)in_sizes; (void)n_in; (void)out_size;
    const float* seq  = (const float*)d_in[0];
    const float* feat = (const float*)d_in[1];
    const float* WaK  = (const float*)d_in[2];
    const float* WaR  = (const float*)d_in[3];
    const float* ba   = (const float*)d_in[4];
    const float* WbK  = (const float*)d_in[5];
    const float* WbR  = (const float*)d_in[6];
    const float* bb   = (const float*)d_in[7];
    const float* Wg   = (const float*)d_in[8];
    const float* bg   = (const float*)d_in[9];
    const float* Wh   = (const float*)d_in[10];
    const float* bh   = (const float*)d_in[11];
    const float* Wc   = (const float*)d_in[12];
    const float* bc   = (const float*)d_in[13];
    const float* Wd   = (const float*)d_in[14];
    const float* bd   = (const float*)d_in[15];
    const float* Wo   = (const float*)d_in[16];
    const float* bo   = (const float*)d_in[17];
    float* out = (float*)d_out;

    xa_gemm<<<dim3(512, 4), 160>>>(seq, WaK, ba);
    recur_k<0><<<512, 160>>>(WaR);
    xb_gemm<<<dim3(512, 4), 160>>>(WbK, bb);
    recur_k<1><<<512, 160>>>(WbR);
    tail_k<<<128, 160>>>(feat, Wg, bg, Wh, bh, Wc, bc, Wd, bd, Wo, bo, out);
}